// round 17
// baseline (speedup 1.0000x reference)
#include <cuda_runtime.h>
#include <cuda_fp16.h>
#include <math.h>

constexpr int BB = 16, LL = 512, DD = 768, HH = 4, AA = 100, DKk = 25, PP = 3;
constexpr int LDW_X = HH + 2 * AA;     // 204
constexpr int LDQ  = 112;              // padded q/k row stride (4 heads x 28)
constexpr int HP   = 28;               // padded head dim
constexpr int LDFH = 320;              // featsh row stride (x|x1|x2|zeros)
constexpr float EPSf = 1e-6f;

using u32 = unsigned int;

// ---------------- device scratch (zero-initialized) ----------------
__device__ __align__(16) __half g_featsh[BB * LL * LDFH];  // cols 0-99 x,100-199 x1,200-299 x2
__device__ __align__(16) __half g_xT [BB * LDQ * LL];      // x^T  [b][d][j]
__device__ __align__(16) __half g_x1T[BB * LDQ * LL];
__device__ __align__(16) __half g_zp [BB * LL * LDQ];      // z, head-padded 28
__device__ __align__(16) __half g_kp [BB * LL * LDQ];      // x,  head-padded 28 (pads stay 0)
__device__ __align__(16) __half g_Mh [LDQ * LDQ];          // (Q^T K)^T padded, fp16
__device__ __align__(16) __half g_P1h[BB * LL * LL];       // sum_h adj_h      (8 MB)
__device__ __align__(16) __half g_Pch[BB * LL * LL];       // sum_h c_h adj_h  (8 MB)
__device__ float g_x1   [BB * LL * AA];                    // fp32 x1 for uv/corr
__device__ float g_U[BB * LL], g_V[BB * LL];
__device__ float g_corrS[BB * 2 * AA];
__device__ float g_pre[512];           // c[4] | b1s[100] | b2s[100] | Cb | w1[100]@208
__device__ float g_pool[BB * AA];

// ---------------- mma.sync m16n8k16 f16 helpers ----------------
__device__ __forceinline__ void mma_f16(float c[4], const u32 a[4], const u32 b[2])
{
    asm volatile(
        "mma.sync.aligned.m16n8k16.row.col.f32.f16.f16.f32 "
        "{%0,%1,%2,%3}, {%4,%5,%6,%7}, {%8,%9}, {%0,%1,%2,%3};\n"
        : "+f"(c[0]), "+f"(c[1]), "+f"(c[2]), "+f"(c[3])
        : "r"(a[0]), "r"(a[1]), "r"(a[2]), "r"(a[3]), "r"(b[0]), "r"(b[1]));
}
__device__ __forceinline__ void ldfrag_a(u32 a[4], const __half* S, int row0, int k0, int lane, int ld)
{
    int r = lane >> 2, c = (lane & 3) * 2;
    a[0] = *(const u32*)(S + (row0 + r    ) * ld + k0 + c    );
    a[1] = *(const u32*)(S + (row0 + r + 8) * ld + k0 + c    );
    a[2] = *(const u32*)(S + (row0 + r    ) * ld + k0 + c + 8);
    a[3] = *(const u32*)(S + (row0 + r + 8) * ld + k0 + c + 8);
}
__device__ __forceinline__ void ldfrag_b(u32 b[2], const __half* S, int n0, int k0, int lane, int ld)
{
    int r = lane >> 2, c = (lane & 3) * 2;
    b[0] = *(const u32*)(S + (n0 + r) * ld + k0 + c    );
    b[1] = *(const u32*)(S + (n0 + r) * ld + k0 + c + 8);
}

// ---------------- M = (Q^T K)^T fp16 + folded weights + zero pool --------
// blocks 0..48: Mh; block 49: pre (c, b1s, b2s, Cb, w1) + pool zero
__global__ void m_pre_kernel(const float* __restrict__ qw, const float* __restrict__ kw,
                             const float* __restrict__ Wxw, const float* __restrict__ Wxb,
                             const float* __restrict__ qb,
                             __half* __restrict__ Mh,
                             float* __restrict__ pre, float* __restrict__ pool)
{
    int t = threadIdx.x;
    if (blockIdx.x < 49) {
        int idx = blockIdx.x * 256 + t;
        if (idx >= LDQ * LDQ) return;
        int e = idx / LDQ, d = idx % LDQ;
        float s = 0.f;
        if (e < AA && d < AA)
            for (int n = 0; n < AA; n++)
                s = fmaf(qw[n * AA + d], kw[n * AA + e], s);
        Mh[idx] = __float2half(s);
        return;
    }
    // block 49: folded weights
    if (t < 4) {
        float s = 0.f;
        for (int g = 0; g < HH; g++) s += Wxw[g * LDW_X + t];
        pre[t] = s;
    } else if (t < 104) {
        int d = t - 4; float s = 0.f;
        for (int g = 0; g < HH; g++) s += Wxw[g * LDW_X + HH + d];
        pre[t] = s;
    } else if (t < 204) {
        int d = t - 104; float s = 0.f;
        for (int g = 0; g < HH; g++) s += Wxw[g * LDW_X + HH + AA + d];
        pre[t] = s;
    } else if (t == 204) {
        pre[204] = Wxb[0] + Wxb[1] + Wxb[2] + Wxb[3];
    }
    if (t < AA) {                      // w1 = K^T qb
        float s = 0.f;
        for (int n = 0; n < AA; n++) s = fmaf(qb[n], kw[n * AA + t], s);
        pre[208 + t] = s;
    }
    for (int e = t; e < BB * AA; e += 256) pool[e] = 0.f;
}

// ---------------- x = LN(seq)@Wxx^T + b, THEN z = x@M + w1 (fused) -------
__global__ __launch_bounds__(256) void gemm_ln_h(
    const float* __restrict__ seq,
    const float* __restrict__ ga, const float* __restrict__ gb,
    const float* __restrict__ W, const float* __restrict__ bias,
    const __half* __restrict__ Mh, const float* __restrict__ pre,
    __half* __restrict__ featsh, __half* __restrict__ xT,
    __half* __restrict__ kpad, __half* __restrict__ zpad)
{
    extern __shared__ __half smh[];
    __half* Ab[2] = { smh,        smh + 7040 };        // 64x40
    __half* Bb[2] = { smh + 2560, smh + 7040 + 2560 }; // 112x40
    __half* Ash = smh;             // phase 2: 64 x 120 (x tile)
    __half* Ws  = smh + 7680;      // phase 2: 112 x 120 (M)
    __shared__ float rmean[64], rinv[64], bsh[112], bzs[112];
    int bm = blockIdx.x * 64;
    int tid = threadIdx.x, lane = tid & 31, warp = tid >> 5;
    int wm = warp >> 1, wn = warp & 1;
    if (tid < 112) {
        bsh[tid] = (tid < AA) ? bias[tid] : 0.f;
        bzs[tid] = (tid < AA) ? pre[208 + tid] : 0.f;
    }
    // LN stats for this block's 64 rows (warp w -> rows 8w..8w+7)
    for (int rr = 0; rr < 8; rr++) {
        int row = warp * 8 + rr;
        const float4* xr = (const float4*)(seq + (size_t)(bm + row) * DD);
        float s = 0.f, s2 = 0.f;
#pragma unroll
        for (int d = lane; d < DD / 4; d += 32) {
            float4 v = xr[d];
            s += v.x + v.y + v.z + v.w;
            s2 = fmaf(v.x, v.x, s2); s2 = fmaf(v.y, v.y, s2);
            s2 = fmaf(v.z, v.z, s2); s2 = fmaf(v.w, v.w, s2);
        }
        for (int o = 16; o; o >>= 1) {
            s  += __shfl_xor_sync(0xffffffffu, s,  o);
            s2 += __shfl_xor_sync(0xffffffffu, s2, o);
        }
        if (lane == 0) {
            float m   = s / (float)DD;
            float var = (s2 - (float)DD * m * m) / (float)(DD - 1);
            rmean[row] = m;
            rinv[row]  = 1.f / (sqrtf(fmaxf(var, 0.f)) + EPSf);
        }
    }
    __syncthreads();
    // stage chunk 0
    for (int e = tid; e < 2048; e += 256) {
        int m = e >> 5, kk = e & 31;
        float v = seq[(size_t)(bm + m) * DD + kk];
        Ab[0][m * 40 + kk] = __float2half(fmaf(ga[kk], (v - rmean[m]) * rinv[m], gb[kk]));
    }
    for (int e = tid; e < 3584; e += 256) {
        int n = e >> 5, kk = e & 31;
        Bb[0][n * 40 + kk] = __float2half((n < AA) ? W[(size_t)n * DD + kk] : 0.f);
    }
    __syncthreads();
    float acc[7][4] = {};
    const int NIT = DD / 32;   // 24
    for (int it = 0; it < NIT; it++) {
        int cur = it & 1;
        float pa[8], pb[14];
        if (it + 1 < NIT) {
            int k1 = (it + 1) * 32;
#pragma unroll
            for (int r2 = 0; r2 < 8; r2++) {
                int e = tid + 256 * r2, m = e >> 5, kk = e & 31, kc = k1 + kk;
                float v = seq[(size_t)(bm + m) * DD + kc];
                pa[r2] = fmaf(ga[kc], (v - rmean[m]) * rinv[m], gb[kc]);
            }
#pragma unroll
            for (int r2 = 0; r2 < 14; r2++) {
                int e = tid + 256 * r2, n = e >> 5, kk = e & 31;
                pb[r2] = (n < AA) ? W[(size_t)n * DD + k1 + kk] : 0.f;
            }
        }
        const __half* As = Ab[cur];
        const __half* Bs = Bb[cur];
#pragma unroll
        for (int ks = 0; ks < 32; ks += 16) {
            u32 a[4], b[2];
            ldfrag_a(a, As, wm * 16, ks, lane, 40);
#pragma unroll
            for (int t = 0; t < 7; t++) {
                ldfrag_b(b, Bs, wn * 56 + 8 * t, ks, lane, 40);
                mma_f16(acc[t], a, b);
            }
        }
        if (it + 1 < NIT) {
            __half* An = Ab[1 - cur];
            __half* Bn = Bb[1 - cur];
#pragma unroll
            for (int r2 = 0; r2 < 8; r2++) { int e = tid + 256 * r2; An[(e >> 5) * 40 + (e & 31)] = __float2half(pa[r2]); }
#pragma unroll
            for (int r2 = 0; r2 < 14; r2++) { int e = tid + 256 * r2; Bn[(e >> 5) * 40 + (e & 31)] = __float2half(pb[r2]); }
        }
        __syncthreads();
    }
    // ---- epilogue: x -> featsh/xT/kpad/smem(Ash); then z = x@M + w1 ----
    // zero Ash pad cols 100..119 (prevent NaN*0 in z mma)
    for (int e = tid; e < 64 * 10; e += 256) {
        int row = e / 10, cp = e % 10;
        *(u32*)&Ash[row * 120 + 100 + 2 * cp] = 0;
    }
    int r = lane >> 2, cb = (lane & 3) * 2;
#pragma unroll
    for (int t = 0; t < 7; t++) {
        int col = wn * 56 + 8 * t + cb;
        if (col >= AA) continue;
        int rl0 = wm * 16 + r, rl1 = rl0 + 8;
        int g0 = bm + rl0, g1 = bm + rl1;
        float o0 = acc[t][0] + bsh[col], o1 = acc[t][1] + bsh[col + 1];
        float o2 = acc[t][2] + bsh[col], o3 = acc[t][3] + bsh[col + 1];
        __half h0 = __float2half(o0), h1 = __float2half(o1);
        __half h2 = __float2half(o2), h3 = __float2half(o3);
        Ash[rl0 * 120 + col] = h0;  Ash[rl0 * 120 + col + 1] = h1;
        Ash[rl1 * 120 + col] = h2;  Ash[rl1 * 120 + col + 1] = h3;
        featsh[(size_t)g0 * LDFH + col]     = h0;
        featsh[(size_t)g0 * LDFH + col + 1] = h1;
        featsh[(size_t)g1 * LDFH + col]     = h2;
        featsh[(size_t)g1 * LDFH + col + 1] = h3;
        int b0i = g0 >> 9, j0 = g0 & 511, b1i = g1 >> 9, j1 = g1 & 511;
        xT[((size_t)b0i * LDQ + col    ) * LL + j0] = h0;
        xT[((size_t)b0i * LDQ + col + 1) * LL + j0] = h1;
        xT[((size_t)b1i * LDQ + col    ) * LL + j1] = h2;
        xT[((size_t)b1i * LDQ + col + 1) * LL + j1] = h3;
        int p0 = (col / 25) * HP + col % 25;
        int p1 = ((col + 1) / 25) * HP + (col + 1) % 25;
        kpad[(size_t)g0 * LDQ + p0] = h0;
        kpad[(size_t)g0 * LDQ + p1] = h1;
        kpad[(size_t)g1 * LDQ + p0] = h2;
        kpad[(size_t)g1 * LDQ + p1] = h3;
    }
    // stage M as B^T [e][d]
    for (int e = tid; e < 112 * 56; e += 256) {
        int n = e / 56, cp = e % 56;
        *(u32*)&Ws[n * 120 + 2 * cp] = *(const u32*)&Mh[n * LDQ + 2 * cp];
    }
    __syncthreads();
    float az[7][4] = {};
#pragma unroll
    for (int ks = 0; ks < 7; ks++) {
        u32 a[4], b[2];
        ldfrag_a(a, Ash, wm * 16, 16 * ks, lane, 120);
#pragma unroll
        for (int t = 0; t < 7; t++) {
            ldfrag_b(b, Ws, wn * 56 + 8 * t, 16 * ks, lane, 120);
            mma_f16(az[t], a, b);
        }
    }
#pragma unroll
    for (int t = 0; t < 7; t++) {
        int col = wn * 56 + 8 * t + cb;
        if (col >= AA) continue;
        int g0 = bm + wm * 16 + r, g1 = g0 + 8;
        int p0 = (col / 25) * HP + col % 25;
        int p1 = ((col + 1) / 25) * HP + (col + 1) % 25;
        zpad[(size_t)g0 * LDQ + p0] = __float2half(az[t][0] + bzs[col]);
        zpad[(size_t)g0 * LDQ + p1] = __float2half(az[t][1] + bzs[col + 1]);
        zpad[(size_t)g1 * LDQ + p0] = __float2half(az[t][2] + bzs[col]);
        zpad[(size_t)g1 * LDQ + p1] = __float2half(az[t][3] + bzs[col + 1]);
    }
}

// ---------------- attention: 32 rows/block, khs staged once per head -----
__global__ __launch_bounds__(512) void attn3_kernel(
    const __half* __restrict__ zpad, const __half* __restrict__ kpad,
    const float* __restrict__ syn, const int* __restrict__ src_mask,
    const float* __restrict__ pre,
    __half* __restrict__ P1, __half* __restrict__ Pc)
{
    extern __shared__ float smf[];
    float* mkf  = smf;          // 512
    float* redm = smf + 512;    // 16x16
    float* reds = smf + 768;    // 16x16
    __half* khs = (__half*)(smf + 1024);   // 512 x 40
    __half* qss = khs + 512 * 40;          // 32 x 40
    int itile = blockIdx.x, b = blockIdx.y;
    int tid = threadIdx.x, lane = tid & 31, warp = tid >> 5;
    int row0 = itile * 32;
    int n0 = warp * 32;
    int r = lane >> 2, cb = (lane & 3) * 2;

    mkf[tid] = src_mask[b * LL + tid] ? 1.f : 0.f;
    float ch[4] = { __ldg(pre), __ldg(pre + 1), __ldg(pre + 2), __ldg(pre + 3) };
    float p1a[2][4][4] = {}, pca[2][4][4] = {};

    for (int h = 0; h < HH; h++) {
        for (int e = tid; e < 512 * 16; e += 512) {
            int j = e >> 4, cp = e & 15;
            u32 v = 0;
            if (cp < 14)
                v = *(const u32*)&kpad[(size_t)(b * LL + j) * LDQ + h * HP + 2 * cp];
            *(u32*)&khs[j * 40 + 2 * cp] = v;
        }
        for (int e = tid; e < 1024; e += 512) {
            int j = e >> 5, d = e & 31;
            qss[j * 40 + d] = (d < DKk)
                ? zpad[(size_t)(b * LL + row0 + j) * LDQ + h * HP + d]
                : __float2half(0.f);
        }
        __syncthreads();
#pragma unroll
        for (int it2 = 0; it2 < 2; it2++) {
            float s[4][4] = {};
#pragma unroll
            for (int ks = 0; ks < 32; ks += 16) {
                u32 a[4], bfr[2];
                ldfrag_a(a, qss, 16 * it2, ks, lane, 40);
#pragma unroll
                for (int t = 0; t < 4; t++) {
                    ldfrag_b(bfr, khs, n0 + 8 * t, ks, lane, 40);
                    mma_f16(s[t], a, bfr);
                }
            }
            int rb = row0 + 16 * it2;
            float mx0 = -1e30f, mx1 = -1e30f;
#pragma unroll
            for (int t = 0; t < 4; t++) {
                int col = n0 + 8 * t + cb;
                float2 sy0 = *(const float2*)&syn[(((size_t)(b * HH + h)) * LL + rb + r    ) * LL + col];
                float2 sy1 = *(const float2*)&syn[(((size_t)(b * HH + h)) * LL + rb + r + 8) * LL + col];
                float m0 = mkf[col], m1 = mkf[col + 1];
                float v0 = ((m0 != 0.f) ? s[t][0] * 0.2f : -1e9f) + sy0.x;
                float v1 = ((m1 != 0.f) ? s[t][1] * 0.2f : -1e9f) + sy0.y;
                float v2 = ((m0 != 0.f) ? s[t][2] * 0.2f : -1e9f) + sy1.x;
                float v3 = ((m1 != 0.f) ? s[t][3] * 0.2f : -1e9f) + sy1.y;
                s[t][0] = v0; s[t][1] = v1; s[t][2] = v2; s[t][3] = v3;
                mx0 = fmaxf(mx0, fmaxf(v0, v1));
                mx1 = fmaxf(mx1, fmaxf(v2, v3));
            }
            mx0 = fmaxf(mx0, __shfl_xor_sync(0xffffffffu, mx0, 1));
            mx0 = fmaxf(mx0, __shfl_xor_sync(0xffffffffu, mx0, 2));
            mx1 = fmaxf(mx1, __shfl_xor_sync(0xffffffffu, mx1, 1));
            mx1 = fmaxf(mx1, __shfl_xor_sync(0xffffffffu, mx1, 2));
            if ((lane & 3) == 0) { redm[r * 16 + warp] = mx0; redm[(r + 8) * 16 + warp] = mx1; }
            __syncthreads();
            float gm0 = -1e30f, gm1 = -1e30f;
#pragma unroll
            for (int w = 0; w < 16; w++) {
                gm0 = fmaxf(gm0, redm[r * 16 + w]);
                gm1 = fmaxf(gm1, redm[(r + 8) * 16 + w]);
            }
            float su0 = 0.f, su1 = 0.f;
#pragma unroll
            for (int t = 0; t < 4; t++) {
                s[t][0] = __expf(s[t][0] - gm0); su0 += s[t][0];
                s[t][1] = __expf(s[t][1] - gm0); su0 += s[t][1];
                s[t][2] = __expf(s[t][2] - gm1); su1 += s[t][2];
                s[t][3] = __expf(s[t][3] - gm1); su1 += s[t][3];
            }
            su0 += __shfl_xor_sync(0xffffffffu, su0, 1);
            su0 += __shfl_xor_sync(0xffffffffu, su0, 2);
            su1 += __shfl_xor_sync(0xffffffffu, su1, 1);
            su1 += __shfl_xor_sync(0xffffffffu, su1, 2);
            if ((lane & 3) == 0) { reds[r * 16 + warp] = su0; reds[(r + 8) * 16 + warp] = su1; }
            __syncthreads();
            float gs0 = 0.f, gs1 = 0.f;
#pragma unroll
            for (int w = 0; w < 16; w++) { gs0 += reds[r * 16 + w]; gs1 += reds[(r + 8) * 16 + w]; }
            float i0 = 1.f / gs0, i1 = 1.f / gs1;
#pragma unroll
            for (int t = 0; t < 4; t++) {
                float a0 = s[t][0] * i0, a1 = s[t][1] * i0;
                float a2 = s[t][2] * i1, a3 = s[t][3] * i1;
                p1a[it2][t][0] += a0; p1a[it2][t][1] += a1;
                p1a[it2][t][2] += a2; p1a[it2][t][3] += a3;
                pca[it2][t][0] += ch[h] * a0; pca[it2][t][1] += ch[h] * a1;
                pca[it2][t][2] += ch[h] * a2; pca[it2][t][3] += ch[h] * a3;
            }
            __syncthreads();   // redm/reds reusable; also guards khs restage next head
        }
    }
#pragma unroll
    for (int it2 = 0; it2 < 2; it2++) {
#pragma unroll
        for (int t = 0; t < 4; t++) {
            int col = n0 + 8 * t + cb;
            size_t o0 = ((size_t)(b * LL) + row0 + 16 * it2 + r    ) * LL + col;
            size_t o1 = ((size_t)(b * LL) + row0 + 16 * it2 + r + 8) * LL + col;
            *(half2*)&P1[o0] = __floats2half2_rn(p1a[it2][t][0], p1a[it2][t][1]);
            *(half2*)&P1[o1] = __floats2half2_rn(p1a[it2][t][2], p1a[it2][t][3]);
            *(half2*)&Pc[o0] = __floats2half2_rn(pca[it2][t][0], pca[it2][t][1]);
            *(half2*)&Pc[o1] = __floats2half2_rn(pca[it2][t][2], pca[it2][t][3]);
        }
    }
}

// ---------------- fused GCN layer: mma P@X -> fp32 W-GEMM -> relu --------
__global__ __launch_bounds__(256) void layer_h(
    const __half* __restrict__ P,
    const __half* __restrict__ XT,
    const float* __restrict__ Ww, const float* __restrict__ Wb,
    __half* __restrict__ featsh, int off,
    float* __restrict__ x1f, __half* __restrict__ x1T,
    int mode,
    const float* __restrict__ V,
    const float* __restrict__ corrS,
    const float* __restrict__ pre)
{
    extern __shared__ float smf[];
    float* Axs = smf;                              // 64 x 104
    __half* hreg = (__half*)(smf + 64 * 104);
    __half* Pb[2] = { hreg,        hreg + 7040 };  // 64 x 40
    __half* Xb[2] = { hreg + 2560, hreg + 7040 + 2560 }; // 112 x 40
    float* Ws2 = smf + 64 * 104;                   // alias, phase 2: 100 x 116
    int bi = blockIdx.x * 64, b = blockIdx.y;
    int tid = threadIdx.x, lane = tid & 31, warp = tid >> 5;
    int wm = warp >> 1, wn = warp & 1;
    const __half* Pbase = P + (size_t)b * LL * LL;
    const __half* Xbase = XT + (size_t)b * LDQ * LL;
    for (int e = tid; e < 1024; e += 256) {
        int m = e >> 4, cp = e & 15;
        *(u32*)&Pb[0][m * 40 + 2 * cp] = *(const u32*)&Pbase[(size_t)(bi + m) * LL + 2 * cp];
    }
    for (int e = tid; e < 1792; e += 256) {
        int n = e >> 4, cp = e & 15;
        *(u32*)&Xb[0][n * 40 + 2 * cp] = *(const u32*)&Xbase[(size_t)n * LL + 2 * cp];
    }
    __syncthreads();
    float acc[7][4] = {};
    const int NIT = LL / 32;   // 16
    for (int it = 0; it < NIT; it++) {
        int cur = it & 1;
        u32 pa[4], pxb[7];
        if (it + 1 < NIT) {
            int k1 = (it + 1) * 32;
#pragma unroll
            for (int r2 = 0; r2 < 4; r2++) {
                int e = tid + 256 * r2, m = e >> 4, cp = e & 15;
                pa[r2] = *(const u32*)&Pbase[(size_t)(bi + m) * LL + k1 + 2 * cp];
            }
#pragma unroll
            for (int r2 = 0; r2 < 7; r2++) {
                int e = tid + 256 * r2, n = e >> 4, cp = e & 15;
                pxb[r2] = *(const u32*)&Xbase[(size_t)n * LL + k1 + 2 * cp];
            }
        }
        const __half* Ps = Pb[cur];
        const __half* Xs = Xb[cur];
#pragma unroll
        for (int ks = 0; ks < 32; ks += 16) {
            u32 a[4], bfr[2];
            ldfrag_a(a, Ps, wm * 16, ks, lane, 40);
#pragma unroll
            for (int t = 0; t < 7; t++) {
                ldfrag_b(bfr, Xs, wn * 56 + 8 * t, ks, lane, 40);
                mma_f16(acc[t], a, bfr);
            }
        }
        if (it + 1 < NIT) {
            __half* Pn = Pb[1 - cur];
            __half* Xn = Xb[1 - cur];
#pragma unroll
            for (int r2 = 0; r2 < 4; r2++) { int e = tid + 256 * r2; *(u32*)&Pn[(e >> 4) * 40 + 2 * (e & 15)] = pa[r2]; }
#pragma unroll
            for (int r2 = 0; r2 < 7; r2++) { int e = tid + 256 * r2; *(u32*)&Xn[(e >> 4) * 40 + 2 * (e & 15)] = pxb[r2]; }
        }
        __syncthreads();
    }
    int r = lane >> 2, cb = (lane & 3) * 2;
    float Cb = mode ? pre[204] : 0.f;
#pragma unroll
    for (int t = 0; t < 7; t++) {
        int col = wn * 56 + 8 * t + cb;
        if (col >= AA) continue;
        int rl0 = wm * 16 + r, rl1 = rl0 + 8;
        float v0 = acc[t][0], v1 = acc[t][1], v2 = acc[t][2], v3 = acc[t][3];
        if (mode) {
            float c0 = corrS[b * 2 * AA + col], c1 = corrS[b * 2 * AA + col + 1];
            float s0 = corrS[b * 2 * AA + AA + col], s1 = corrS[b * 2 * AA + AA + col + 1];
            float vr0 = V[b * LL + bi + rl0] + Cb;
            float vr1 = V[b * LL + bi + rl1] + Cb;
            v0 += c0 + vr0 * s0;  v1 += c1 + vr0 * s1;
            v2 += c0 + vr1 * s0;  v3 += c1 + vr1 * s1;
        }
        Axs[rl0 * 104 + col] = v0 * 0.25f;  Axs[rl0 * 104 + col + 1] = v1 * 0.25f;
        Axs[rl1 * 104 + col] = v2 * 0.25f;  Axs[rl1 * 104 + col + 1] = v3 * 0.25f;
    }
    for (int e = tid; e < AA * AA; e += 256) {
        int n = e / AA, kk = e % AA;
        Ws2[kk * 116 + n] = Ww[e];
    }
    for (int e = tid; e < AA * 16; e += 256) {
        int kk = e >> 4, n = AA + (e & 15);
        Ws2[kk * 116 + n] = 0.f;
    }
    __syncthreads();
    int tx = tid & 15, ty = tid >> 4;
    float acc2[4][7] = {};
#pragma unroll 4
    for (int kk = 0; kk < AA; kk++) {
        float a[4], w[7];
#pragma unroll
        for (int i = 0; i < 4; i++) a[i] = Axs[(ty + 16 * i) * 104 + kk];
#pragma unroll
        for (int j = 0; j < 7; j++) w[j] = Ws2[kk * 116 + tx + 16 * j];
#pragma unroll
        for (int i = 0; i < 4; i++)
#pragma unroll
            for (int j = 0; j < 7; j++)
                acc2[i][j] = fmaf(a[i], w[j], acc2[i][j]);
    }
#pragma unroll
    for (int i = 0; i < 4; i++) {
        int rowl = ty + 16 * i;
        size_t grow = (size_t)b * LL + bi + rowl;
#pragma unroll
        for (int j = 0; j < 7; j++) {
            int col = tx + 16 * j;
            if (col < AA) {
                float v = fmaxf(acc2[i][j] + Wb[col], 0.f);
                featsh[grow * LDFH + off + col] = __float2half(v);
                if (mode == 0) {
                    x1f[grow * AA + col] = v;
                    x1T[((size_t)b * LDQ + col) * LL + bi + rowl] = __float2half(v);
                }
            }
        }
    }
}

// ---------------- U, V per row ----------------
__global__ void uv_kernel(const float* __restrict__ x1,
                          const float* __restrict__ pre,
                          float* __restrict__ U, float* __restrict__ V)
{
    __shared__ float b1s[AA], b2s[AA];
    int tid = threadIdx.x;
    for (int e = tid; e < AA; e += 256) { b1s[e] = pre[4 + e]; b2s[e] = pre[104 + e]; }
    __syncthreads();
    int row = blockIdx.x * 8 + (tid >> 5);
    int lane = tid & 31;
    const float* xr = x1 + (size_t)row * AA;
    float u = 0.f, v = 0.f;
    for (int d = lane; d < AA; d += 32) {
        float xv = xr[d];
        u = fmaf(xv, b1s[d], u);
        v = fmaf(xv, b2s[d], v);
    }
    for (int o = 16; o; o >>= 1) {
        u += __shfl_xor_sync(0xffffffffu, u, o);
        v += __shfl_xor_sync(0xffffffffu, v, o);
    }
    if (lane == 0) { U[row] = u; V[row] = v; }
}

// ---------------- corr / S ----------------
__global__ void corrS_kernel(const float* __restrict__ x1,
                             const float* __restrict__ U,
                             float* __restrict__ corrS)
{
    __shared__ float sc[2][128], ss[2][128];
    int b = blockIdx.x, tid = threadIdx.x;
    int d = tid & 127, half = tid >> 7;
    float c = 0.f, s = 0.f;
    if (d < AA) {
        for (int j = half; j < LL; j += 2) {
            float xv = x1[((size_t)b * LL + j) * AA + d];
            c = fmaf(U[b * LL + j], xv, c);
            s += xv;
        }
    }
    sc[half][d] = c; ss[half][d] = s;
    __syncthreads();
    if (half == 0 && d < AA) {
        corrS[b * 2 * AA + d]      = sc[0][d] + sc[1][d];
        corrS[b * 2 * AA + AA + d] = ss[0][d] + ss[1][d];
    }
}

// ---------------- agg mma GEMM + relu + fused pool ----------------
__global__ __launch_bounds__(256) void agg_h(
    const __half* __restrict__ featsh,
    const float* __restrict__ W,      // agg_w, 100 x 300
    const float* __restrict__ bias,
    float* __restrict__ pool)
{
    extern __shared__ float smf[];
    float* red = smf;                          // 8 x 112
    __half* hreg = (__half*)(smf + 896);
    __half* Fb[2] = { hreg,        hreg + 7040 };
    __half* Bb[2] = { hreg + 2560, hreg + 7040 + 2560 };
    __shared__ float bsh[112];
    int bm = blockIdx.x * 64;
    int b = bm >> 9;
    int tid = threadIdx.x, lane = tid & 31, warp = tid >> 5;
    int wm = warp >> 1, wn = warp & 1;
    if (tid < 112) bsh[tid] = (tid < AA) ? bias[tid] : 0.f;
    for (int e = tid; e < 896; e += 256) red[e] = 0.f;
    for (int e = tid; e < 1024; e += 256) {
        int m = e >> 4, cp = e & 15;
        *(u32*)&Fb[0][m * 40 + 2 * cp] = *(const u32*)&featsh[(size_t)(bm + m) * LDFH + 2 * cp];
    }
    for (int e = tid; e < 1792; e += 256) {
        int n = e >> 4, cp = e & 15;
        int kk = 2 * cp;
        float w0 = (n < AA && kk     < 300) ? W[(size_t)n * 300 + kk]     : 0.f;
        float w1 = (n < AA && kk + 1 < 300) ? W[(size_t)n * 300 + kk + 1] : 0.f;
        *(half2*)&Bb[0][n * 40 + kk] = __floats2half2_rn(w0, w1);
    }
    __syncthreads();
    float acc[7][4] = {};
    const int NIT = 10;
    for (int it = 0; it < NIT; it++) {
        int cur = it & 1;
        u32 pf[4]; float pw0[7], pw1[7];
        if (it + 1 < NIT) {
            int k1 = (it + 1) * 32;
#pragma unroll
            for (int r2 = 0; r2 < 4; r2++) {
                int e = tid + 256 * r2, m = e >> 4, cp = e & 15;
                pf[r2] = *(const u32*)&featsh[(size_t)(bm + m) * LDFH + k1 + 2 * cp];
            }
#pragma unroll
            for (int r2 = 0; r2 < 7; r2++) {
                int e = tid + 256 * r2, n = e >> 4, cp = e & 15;
                int kk = k1 + 2 * cp;
                pw0[r2] = (n < AA && kk     < 300) ? W[(size_t)n * 300 + kk]     : 0.f;
                pw1[r2] = (n < AA && kk + 1 < 300) ? W[(size_t)n * 300 + kk + 1] : 0.f;
            }
        }
        const __half* Fs = Fb[cur];
        const __half* Bs = Bb[cur];
#pragma unroll
        for (int ks = 0; ks < 32; ks += 16) {
            u32 a[4], bfr[2];
            ldfrag_a(a, Fs, wm * 16, ks, lane, 40);
#pragma unroll
            for (int t = 0; t < 7; t++) {
                ldfrag_b(bfr, Bs, wn * 56 + 8 * t, ks, lane, 40);
                mma_f16(acc[t], a, bfr);
            }
        }
        if (it + 1 < NIT) {
            __half* Fn = Fb[1 - cur];
            __half* Bn = Bb[1 - cur];
#pragma unroll
            for (int r2 = 0; r2 < 4; r2++) { int e = tid + 256 * r2; *(u32*)&Fn[(e >> 4) * 40 + 2 * (e & 15)] = pf[r2]; }
#pragma unroll
            for (int r2 = 0; r2 < 7; r2++) { int e = tid + 256 * r2; *(half2*)&Bn[(e >> 4) * 40 + 2 * (e & 15)] = __floats2half2_rn(pw0[r2], pw1[r2]); }
        }
        __syncthreads();
    }
    int cb = (lane & 3) * 2;
#pragma unroll
    for (int t = 0; t < 7; t++) {
        int col = wn * 56 + 8 * t + cb;
        float s0 = fmaxf(acc[t][0] + bsh[col], 0.f)     + fmaxf(acc[t][2] + bsh[col], 0.f);
        float s1 = fmaxf(acc[t][1] + bsh[col + 1], 0.f) + fmaxf(acc[t][3] + bsh[col + 1], 0.f);
        s0 += __shfl_xor_sync(0xffffffffu, s0, 4);
        s0 += __shfl_xor_sync(0xffffffffu, s0, 8);
        s0 += __shfl_xor_sync(0xffffffffu, s0, 16);
        s1 += __shfl_xor_sync(0xffffffffu, s1, 4);
        s1 += __shfl_xor_sync(0xffffffffu, s1, 8);
        s1 += __shfl_xor_sync(0xffffffffu, s1, 16);
        if (lane < 4) {
            red[warp * 112 + col]     = s0;
            red[warp * 112 + col + 1] = s1;
        }
    }
    __syncthreads();
    if (tid < AA) {
        int w0 = (tid < 56) ? 0 : 1;
        float tot = 0.f;
#pragma unroll
        for (int w = 0; w < 4; w++) tot += red[(w0 + 2 * w) * 112 + tid];
        atomicAdd(&pool[b * AA + tid], tot);
    }
}

// ---------------- logits ----------------
__global__ void logits_kernel(const float* __restrict__ pool,
                              const int* __restrict__ mask_ids,
                              const float* __restrict__ cls_w,
                              const float* __restrict__ cls_b,
                              float* __restrict__ out)
{
    __shared__ float linv[BB];
    __shared__ float pr[BB * AA];
    __shared__ float cw[PP * AA];
    int tid = threadIdx.x;              // 512
    int warp = tid >> 5, lane = tid & 31;
    if (warp < BB) {
        int ms = 0;
#pragma unroll
        for (int t = 0; t < 16; t++) ms += mask_ids[warp * LL + lane + 32 * t];
        for (int o = 16; o; o >>= 1) ms += __shfl_xor_sync(0xffffffffu, ms, o);
        if (lane == 0) linv[warp] = 1.f / fmaxf((float)ms, 1.f);
    }
    for (int e = tid; e < BB * AA; e += 512) pr[e] = pool[e];
    for (int e = tid; e < PP * AA; e += 512) cw[e] = cls_w[e];
    __syncthreads();
    if (tid < BB * PP) {
        int b = tid / PP, p = tid % PP;
        float s0 = 0.f, s1 = 0.f, s2 = 0.f, s3 = 0.f;
#pragma unroll
        for (int d = 0; d < AA; d += 4) {
            s0 = fmaf(pr[b * AA + d + 0], cw[p * AA + d + 0], s0);
            s1 = fmaf(pr[b * AA + d + 1], cw[p * AA + d + 1], s1);
            s2 = fmaf(pr[b * AA + d + 2], cw[p * AA + d + 2], s2);
            s3 = fmaf(pr[b * AA + d + 3], cw[p * AA + d + 3], s3);
        }
        out[tid] = cls_b[p] + linv[b] * (s0 + s1 + s2 + s3);
    }
}

// ---------------- launch ----------------
extern "C" void kernel_launch(void* const* d_in, const int* in_sizes, int n_in,
                              void* d_out, int out_size)
{
    const float* seq      = (const float*)d_in[0];
    const float* syn      = (const float*)d_in[1];
    const float* ln_a     = (const float*)d_in[2];
    const float* ln_b     = (const float*)d_in[3];
    const float* Wxx_w    = (const float*)d_in[4];
    const float* Wxx_b    = (const float*)d_in[5];
    const float* q_w      = (const float*)d_in[6];
    const float* q_b      = (const float*)d_in[7];
    const float* k_w      = (const float*)d_in[8];
    const float* k_b      = (const float*)d_in[9];
    const float* W_w      = (const float*)d_in[10];
    const float* W_b      = (const float*)d_in[11];
    const float* Wx_w     = (const float*)d_in[12];
    const float* Wx_b     = (const float*)d_in[13];
    const float* agg_w    = (const float*)d_in[14];
    const float* agg_b    = (const float*)d_in[15];
    const float* cls_w    = (const float*)d_in[16];
    const float* cls_b    = (const float*)d_in[17];
    const int*   mask_ids = (const int*)d_in[18];
    const int*   src_mask = (const int*)d_in[19];
    float* out = (float*)d_out;

    __half *featsh, *xT, *x1T, *zp, *kp, *Mh, *P1h, *Pch;
    float *x1f, *U, *V, *corrS, *pre, *pool;
    cudaGetSymbolAddress((void**)&featsh, g_featsh);
    cudaGetSymbolAddress((void**)&xT,     g_xT);
    cudaGetSymbolAddress((void**)&x1T,    g_x1T);
    cudaGetSymbolAddress((void**)&zp,     g_zp);
    cudaGetSymbolAddress((void**)&kp,     g_kp);
    cudaGetSymbolAddress((void**)&Mh,     g_Mh);
    cudaGetSymbolAddress((void**)&P1h,    g_P1h);
    cudaGetSymbolAddress((void**)&Pch,    g_Pch);
    cudaGetSymbolAddress((void**)&x1f,    g_x1);
    cudaGetSymbolAddress((void**)&U,      g_U);
    cudaGetSymbolAddress((void**)&V,      g_V);
    cudaGetSymbolAddress((void**)&corrS,  g_corrS);
    cudaGetSymbolAddress((void**)&pre,    g_pre);
    cudaGetSymbolAddress((void**)&pool,   g_pool);

    const int M = BB * LL;           // 8192
    const int GM = M / 64;           // 128

    const int GEMMLN_SMEM = (7680 + 13440) * 2;                   // 42,240 (z-phase max)
    const int ATTN_SMEM   = 1024 * 4 + (512 * 40 + 32 * 40) * 2;  // 47,616
    const int LAYER_SMEM  = 64 * 104 * 4 + 100 * 116 * 4;         // 73,024
    const int AGG_SMEM    = 896 * 4 + 2 * 7040 * 2;               // 31,744
    cudaFuncSetAttribute(gemm_ln_h,   cudaFuncAttributeMaxDynamicSharedMemorySize, GEMMLN_SMEM);
    cudaFuncSetAttribute(attn3_kernel,cudaFuncAttributeMaxDynamicSharedMemorySize, ATTN_SMEM);
    cudaFuncSetAttribute(layer_h,     cudaFuncAttributeMaxDynamicSharedMemorySize, LAYER_SMEM);
    cudaFuncSetAttribute(agg_h,       cudaFuncAttributeMaxDynamicSharedMemorySize, AGG_SMEM);

    // 0) M = (Q^T K)^T fp16 + folded weights + zero pool (one launch)
    m_pre_kernel<<<50, 256>>>(q_w, k_w, Wx_w, Wx_b, q_b, Mh, pre, pool);
    // 1) x = LN(seq)@Wxx^T + b, then z = x@M + w1 (fused)
    gemm_ln_h<<<GM, 256, GEMMLN_SMEM>>>(seq, ln_a, ln_b, Wxx_w, Wxx_b, Mh, pre,
                                        featsh, xT, kp, zp);
    // 2) attention (32 rows/block): scores = z . x -> P1h, Pch
    attn3_kernel<<<dim3(LL / 32, BB), 512, ATTN_SMEM>>>(zp, kp, syn, src_mask, pre, P1h, Pch);
    // 3) layer 1
    layer_h<<<dim3(LL / 64, BB), 256, LAYER_SMEM>>>(P1h, xT, W_w, W_b, featsh, AA,
                                                    x1f, x1T, 0, nullptr, nullptr, pre);
    // 4) rank-1 corrections
    uv_kernel<<<M / 8, 256>>>(x1f, pre, U, V);
    corrS_kernel<<<BB, 256>>>(x1f, U, corrS);
    // 5) layer 2
    layer_h<<<dim3(LL / 64, BB), 256, LAYER_SMEM>>>(Pch, x1T, W_w, W_b, featsh, 2 * AA,
                                                    nullptr, nullptr, 1, V, corrS, pre);
    // 6) aggregate + relu + masked mean pool
    agg_h<<<GM, 256, AGG_SMEM>>>(featsh, agg_w, agg_b, pool);
    // 7) logits
    logits_kernel<<<1, 512>>>(pool, mask_ids, cls_w, cls_b, out);
}